// round 1
// baseline (speedup 1.0000x reference)
#include <cuda_runtime.h>
#include <math.h>

// Problem constants (fixed by the reference).
#define BB 64
#define TT 188
#define VV 32000
#define ROWS (BB * TT)
#define BETA 2.0f

#define ROW_THREADS 512
#define ROW_WARPS (ROW_THREADS / 32)

// Scratch for per-row losses (no device allocation allowed).
__device__ float g_row_loss[ROWS];

// One block per (b, t) row. Streams V=32000 floats with float4 loads,
// computes argmax (first-index tie-break, matching jnp.argmax), then
// row loss = mask * weight * (-log(score[target])).
__global__ __launch_bounds__(ROW_THREADS)
void row_loss_kernel(const float* __restrict__ scores,
                     const int*   __restrict__ targets,
                     const int*   __restrict__ lengths) {
    const int row = blockIdx.x;
    const int b = row / TT;
    const int t = row % TT;

    // Masked rows: contribute 0 and skip the 128 KB read entirely.
    if (t >= __ldg(&lengths[b])) {
        if (threadIdx.x == 0) g_row_loss[row] = 0.0f;
        return;
    }

    const size_t base = (size_t)row * VV;
    const float4* __restrict__ p = (const float4*)(scores + base);

    float maxv = -1.0f;   // scores are strictly positive probabilities
    int   maxi = VV;

    // 8000 float4 per row; strided over 512 threads -> 15.625 iters/thread.
    #pragma unroll 4
    for (int i = threadIdx.x; i < VV / 4; i += ROW_THREADS) {
        float4 v = p[i];
        const int idx = i * 4;
        // Within-thread indices are strictly increasing, so strict '>' gives
        // first-index tie-break automatically.
        if (v.x > maxv) { maxv = v.x; maxi = idx;     }
        if (v.y > maxv) { maxv = v.y; maxi = idx + 1; }
        if (v.z > maxv) { maxv = v.z; maxi = idx + 2; }
        if (v.w > maxv) { maxv = v.w; maxi = idx + 3; }
    }

    // Warp reduction: keep max value; on tie keep smaller index.
    #pragma unroll
    for (int off = 16; off > 0; off >>= 1) {
        float ov = __shfl_down_sync(0xffffffffu, maxv, off);
        int   oi = __shfl_down_sync(0xffffffffu, maxi, off);
        if (ov > maxv || (ov == maxv && oi < maxi)) { maxv = ov; maxi = oi; }
    }

    __shared__ float s_val[ROW_WARPS];
    __shared__ int   s_idx[ROW_WARPS];
    const int lane = threadIdx.x & 31;
    const int wid  = threadIdx.x >> 5;
    if (lane == 0) { s_val[wid] = maxv; s_idx[wid] = maxi; }
    __syncthreads();

    if (wid == 0) {
        maxv = (lane < ROW_WARPS) ? s_val[lane] : -1.0f;
        maxi = (lane < ROW_WARPS) ? s_idx[lane] : VV;
        #pragma unroll
        for (int off = 8; off > 0; off >>= 1) {
            float ov = __shfl_down_sync(0xffffffffu, maxv, off);
            int   oi = __shfl_down_sync(0xffffffffu, maxi, off);
            if (ov > maxv || (ov == maxv && oi < maxi)) { maxv = ov; maxi = oi; }
        }
        if (lane == 0) {
            const int target = __ldg(&targets[row]);
            const float gathered = __ldg(&scores[base + (size_t)target]);
            const float w = (maxi == target && target != 0) ? BETA : 1.0f;
            g_row_loss[row] = -w * logf(gathered);
        }
    }
}

// Deterministic single-block tree reduction of the 12032 row losses.
__global__ __launch_bounds__(256)
void reduce_kernel(float* __restrict__ out) {
    __shared__ float s[256];
    float sum = 0.0f;
    for (int i = threadIdx.x; i < ROWS; i += 256) sum += g_row_loss[i];
    s[threadIdx.x] = sum;
    __syncthreads();
    #pragma unroll
    for (int k = 128; k > 0; k >>= 1) {
        if (threadIdx.x < k) s[threadIdx.x] += s[threadIdx.x + k];
        __syncthreads();
    }
    if (threadIdx.x == 0) out[0] = s[0] / (float)BB;
}

extern "C" void kernel_launch(void* const* d_in, const int* in_sizes, int n_in,
                              void* d_out, int out_size) {
    const float* scores  = (const float*)d_in[0];  // [B,T,V] fp32
    const int*   targets = (const int*)  d_in[1];  // [B,T]   int32
    const int*   lengths = (const int*)  d_in[2];  // [B]     int32
    float* out = (float*)d_out;                    // [1]     fp32

    row_loss_kernel<<<ROWS, ROW_THREADS>>>(scores, targets, lengths);
    reduce_kernel<<<1, 256>>>(out);
}